// round 1
// baseline (speedup 1.0000x reference)
#include <cuda_runtime.h>
#include <math.h>

#define Bz   1024
#define Nn   16
#define OBS  128
#define ACTD 32
#define RH   256
#define SH   256
#define KK   8
#define Ee   240
#define BN_  (Bz*Nn)   // 16384

// ---------------- scratch (__device__ globals; no allocation) ----------------
__device__ float g_x   [BN_*129];
__device__ float g_gx  [BN_*768];
__device__ float g_gh  [BN_*768];
__device__ float g_eHs [BN_*SH];
__device__ float g_eHr [BN_*SH];
__device__ float g_dHs [BN_*SH];
__device__ float g_dHr [BN_*SH];
__device__ float g_S   [BN_*SH];
__device__ float g_msgs[BN_*KK*OBS];
__device__ float g_ai  [BN_*2*OBS];
__device__ float g_h1a [BN_*2*OBS];
__device__ float g_h1c [BN_*2*OBS];

// ---------------- generic tiled fp32 GEMM: C = (A @ B^T + bias*biasMul)*scale, optional relu
// A: [M,K] row-major lda; B: [N,K] row-major ldb; batched via blockIdx.z strides.
__global__ __launch_bounds__(256) void gemm_k(
    const float* __restrict__ A, int lda, long long sA,
    const float* __restrict__ Bm, int ldb, long long sB,
    const float* __restrict__ bias, long long sBias, float biasMul,
    float* __restrict__ C, int ldc, long long sC,
    int M, int N, int K, float scale, int relu)
{
    __shared__ float As[64][17];
    __shared__ float Bs[64][17];
    int bz = blockIdx.z;
    A  += (long long)bz * sA;
    Bm += (long long)bz * sB;
    C  += (long long)bz * sC;
    const float* bp = bias ? bias + (long long)bz * sBias : (const float*)0;

    int tid = threadIdx.x;
    int tx = tid & 15, ty = tid >> 4;
    int row0 = blockIdx.y * 64;
    int col0 = blockIdx.x * 64;
    float acc[4][4];
    #pragma unroll
    for (int u = 0; u < 4; u++)
        #pragma unroll
        for (int v = 0; v < 4; v++) acc[u][v] = 0.f;

    for (int k0 = 0; k0 < K; k0 += 16) {
        #pragma unroll
        for (int p = 0; p < 4; p++) {
            int t  = tid + p * 256;
            int r  = t >> 4;
            int kk = t & 15;
            int gk = k0 + kk;
            int gr = row0 + r;
            As[r][kk] = (gr < M && gk < K) ? A[(long long)gr * lda + gk] : 0.f;
            int gc = col0 + r;
            Bs[r][kk] = (gc < N && gk < K) ? Bm[(long long)gc * ldb + gk] : 0.f;
        }
        __syncthreads();
        #pragma unroll
        for (int kk = 0; kk < 16; kk++) {
            float a[4], b[4];
            #pragma unroll
            for (int u = 0; u < 4; u++) a[u] = As[ty*4+u][kk];
            #pragma unroll
            for (int v = 0; v < 4; v++) b[v] = Bs[tx*4+v][kk];
            #pragma unroll
            for (int u = 0; u < 4; u++)
                #pragma unroll
                for (int v = 0; v < 4; v++) acc[u][v] += a[u] * b[v];
        }
        __syncthreads();
    }
    #pragma unroll
    for (int u = 0; u < 4; u++) {
        int gr = row0 + ty*4 + u;
        if (gr >= M) continue;
        #pragma unroll
        for (int v = 0; v < 4; v++) {
            int gc = col0 + tx*4 + v;
            if (gc >= N) continue;
            float val = acc[u][v];
            if (bp) val += bp[gc] * biasMul;
            val *= scale;
            if (relu) val = fmaxf(val, 0.f);
            C[(long long)gr * ldc + gc] = val;
        }
    }
}

// ---------------- build x = concat(obs, reward) per row ----------------
__global__ void buildx_k(const float* __restrict__ obs, const float* __restrict__ rew,
                         float* __restrict__ x)
{
    int idx = blockIdx.x * 256 + threadIdx.x;
    if (idx >= BN_ * 129) return;
    int m = idx / 129, c = idx - m * 129;
    x[idx] = (c < OBS) ? obs[m * OBS + c] : rew[m];
}

// ---------------- GRU gates ----------------
__global__ void gru_gate_k(const float* __restrict__ gx, const float* __restrict__ gh,
                           const float* __restrict__ h0, float* __restrict__ h)
{
    int idx = blockIdx.x * blockDim.x + threadIdx.x;
    if (idx >= BN_ * RH) return;
    int m = idx >> 8;
    int c = idx & 255;
    const float* px = gx + (long long)m * 768;
    const float* ph = gh + (long long)m * 768;
    float r  = 1.f / (1.f + expf(-(px[c]       + ph[c])));
    float z  = 1.f / (1.f + expf(-(px[c + 256] + ph[c + 256])));
    float nc = tanhf(px[c + 512] + r * ph[c + 512]);
    h[idx] = (1.f - z) * nc + z * h0[idx];
}

// ---------------- fused per-batch edge kernel ----------------
// warp w handles receivers i = 2w, 2w+1; 15 senders each.
// enc: logits = relu(eHs[j] + eHr[i]) @ w2^T + b2 -> softmax -> rel
// dec: S[i] += relu(dHs[j] + dHr[i])     (b1's already folded into *Hr via GEMM bias)
__global__ __launch_bounds__(256) void edge_k(
    const float* __restrict__ eHs, const float* __restrict__ eHr,
    const float* __restrict__ dHs, const float* __restrict__ dHr,
    const float* __restrict__ w2, const float* __restrict__ b2,
    float* __restrict__ rel, float* __restrict__ Sout)
{
    __shared__ float sW2[KK * SH];
    __shared__ float sS[Nn][SH];
    int b = blockIdx.x;
    int tid = threadIdx.x;
    for (int i = tid; i < KK * SH; i += 256) sW2[i] = w2[i];
    for (int i = tid; i < Nn * SH; i += 256) (&sS[0][0])[i] = 0.f;
    __syncthreads();

    int w = tid >> 5, lane = tid & 31;
    long long base = (long long)b * Nn * SH;
    for (int ii = 0; ii < 2; ii++) {
        int i = w * 2 + ii;
        float eR[8], dR[8];
        #pragma unroll
        for (int q = 0; q < 8; q++) {
            int c = lane + 32 * q;
            eR[q] = eHr[base + i * SH + c];
            dR[q] = dHr[base + i * SH + c];
        }
        for (int j = 0; j < Nn; j++) {
            if (j == i) continue;
            float part[KK];
            #pragma unroll
            for (int k = 0; k < KK; k++) part[k] = 0.f;
            #pragma unroll
            for (int q = 0; q < 8; q++) {
                int c = lane + 32 * q;
                float pe = eHs[base + j * SH + c] + eR[q];
                pe = fmaxf(pe, 0.f);
                #pragma unroll
                for (int k = 0; k < KK; k++) part[k] += pe * sW2[k * SH + c];
                float pd = dHs[base + j * SH + c] + dR[q];
                pd = fmaxf(pd, 0.f);
                sS[i][c] += pd;
            }
            #pragma unroll
            for (int k = 0; k < KK; k++) {
                #pragma unroll
                for (int off = 16; off; off >>= 1)
                    part[k] += __shfl_xor_sync(0xffffffffu, part[k], off);
                part[k] += b2[k];
            }
            if (lane == 0) {
                float mx = part[0];
                #pragma unroll
                for (int k = 1; k < KK; k++) mx = fmaxf(mx, part[k]);
                float e_[KK], s = 0.f;
                #pragma unroll
                for (int k = 0; k < KK; k++) { e_[k] = expf(part[k] - mx); s += e_[k]; }
                float inv = 1.f / s;
                int jj = (j < i) ? j : j - 1;
                long long eo = ((long long)b * Ee + i * 15 + jj) * KK;
                #pragma unroll
                for (int k = 0; k < KK; k++) rel[eo + k] = e_[k] * inv;
            }
        }
    }
    __syncthreads();
    for (int i = tid; i < Nn * SH; i += 256)
        Sout[base + i] = (&sS[0][0])[i];
}

// ---------------- message aggregation + build ai = [obs, message] ----------------
__global__ __launch_bounds__(256) void message_k(
    const float* __restrict__ rel, const float* __restrict__ msgs,
    const float* __restrict__ obs, float* __restrict__ ai)
{
    __shared__ float sRel[Ee * KK];  // 1920
    int b = blockIdx.x;
    int tid = threadIdx.x;
    for (int i = tid; i < Ee * KK; i += 256) sRel[i] = rel[(long long)b * Ee * KK + i];
    __syncthreads();

    int d = tid & 127;
    int g = tid >> 7;
    float acc[8];
    #pragma unroll
    for (int ii = 0; ii < 8; ii++) acc[ii] = 0.f;
    long long mb = (long long)b * Nn * KK * OBS;
    for (int j = 0; j < Nn; j++) {
        float mj[KK];
        #pragma unroll
        for (int k = 0; k < KK; k++) mj[k] = msgs[mb + (j * KK + k) * OBS + d];
        #pragma unroll
        for (int ii = 0; ii < 8; ii++) {
            int i = g * 8 + ii;
            if (i == j) continue;
            int jj = (j < i) ? j : j - 1;
            const float* r = &sRel[(i * 15 + jj) * KK];
            float a = acc[ii];
            #pragma unroll
            for (int k = 0; k < KK; k++) a += r[k] * mj[k];
            acc[ii] = a;
        }
    }
    long long ab = (long long)b * Nn * 2 * OBS;
    #pragma unroll
    for (int ii = 0; ii < 8; ii++) {
        int i = g * 8 + ii;
        ai[ab + i * 2 * OBS + OBS + d] = acc[ii];
    }
    for (int idx = tid; idx < Nn * OBS; idx += 256) {
        int i = idx >> 7, dd = idx & 127;
        ai[ab + i * 2 * OBS + dd] = obs[(long long)b * Nn * OBS + idx];
    }
}

// ---------------- critic layer 2 (N=1): one warp per (b,n) dot ----------------
__global__ void critic2_k(const float* __restrict__ h1, const float* __restrict__ w2,
                          const float* __restrict__ b2v, float* __restrict__ out)
{
    int w = (blockIdx.x * blockDim.x + threadIdx.x) >> 5;
    int lane = threadIdx.x & 31;
    if (w >= BN_) return;
    int n = w & 15;
    float s = 0.f;
    #pragma unroll
    for (int q = 0; q < 8; q++) {
        int c = lane + 32 * q;
        s += h1[(long long)w * 256 + c] * w2[n * 256 + c];
    }
    #pragma unroll
    for (int off = 16; off; off >>= 1) s += __shfl_xor_sync(0xffffffffu, s, off);
    if (lane == 0) out[w] = s + b2v[n];
}

// ---------------- launch ----------------
extern "C" void kernel_launch(void* const* d_in, const int* in_sizes, int n_in,
                              void* d_out, int out_size)
{
    const float* obs    = (const float*)d_in[0];
    const float* rew    = (const float*)d_in[1];
    const float* h0     = (const float*)d_in[2];
    const float* w_ih   = (const float*)d_in[3];
    const float* w_hh   = (const float*)d_in[4];
    const float* b_ih   = (const float*)d_in[5];
    const float* b_hh   = (const float*)d_in[6];
    const float* enc_w1 = (const float*)d_in[7];
    const float* enc_b1 = (const float*)d_in[8];
    const float* enc_w2 = (const float*)d_in[9];
    const float* enc_b2 = (const float*)d_in[10];
    const float* dec_w1 = (const float*)d_in[11];
    const float* dec_b1 = (const float*)d_in[12];
    const float* dec_w2 = (const float*)d_in[13];
    const float* dec_b2 = (const float*)d_in[14];
    const float* msg_w  = (const float*)d_in[15];
    const float* msg_b  = (const float*)d_in[16];
    const float* aw1    = (const float*)d_in[17];
    const float* ab1    = (const float*)d_in[18];
    const float* aw2    = (const float*)d_in[19];
    const float* ab2    = (const float*)d_in[20];
    const float* cw1    = (const float*)d_in[21];
    const float* cb1    = (const float*)d_in[22];
    const float* cw2    = (const float*)d_in[23];
    const float* cb2    = (const float*)d_in[24];
    float* out = (float*)d_out;

    float *px, *pgx, *pgh, *peHs, *peHr, *pdHs, *pdHr, *pS, *pmsgs, *pai, *ph1a, *ph1c;
    cudaGetSymbolAddress((void**)&px,    g_x);
    cudaGetSymbolAddress((void**)&pgx,   g_gx);
    cudaGetSymbolAddress((void**)&pgh,   g_gh);
    cudaGetSymbolAddress((void**)&peHs,  g_eHs);
    cudaGetSymbolAddress((void**)&peHr,  g_eHr);
    cudaGetSymbolAddress((void**)&pdHs,  g_dHs);
    cudaGetSymbolAddress((void**)&pdHr,  g_dHr);
    cudaGetSymbolAddress((void**)&pS,    g_S);
    cudaGetSymbolAddress((void**)&pmsgs, g_msgs);
    cudaGetSymbolAddress((void**)&pai,   g_ai);
    cudaGetSymbolAddress((void**)&ph1a,  g_h1a);
    cudaGetSymbolAddress((void**)&ph1c,  g_h1c);

    float* actor  = out;                 // [B,N,32]   524288
    float* critic = out + 524288;        // [B,N,1]    16384
    float* scm    = out + 540672;        // [B,N,129]  2113536
    float* rel    = out + 2654208;       // [B,E,8]    1966080
    float* hid    = out + 4620288;       // [1,B*N,256] 4194304

    buildx_k<<<(BN_ * 129 + 255) / 256, 256>>>(obs, rew, px);

    // GRU: gx = x @ Wih^T + b_ih ; gh = h0 @ Whh^T + b_hh
    gemm_k<<<dim3(12, 256, 1), 256>>>(px, 129, 0, w_ih, 129, 0, b_ih, 0, 1.f,
                                      pgx, 768, 0, BN_, 768, 129, 1.f, 0);
    gemm_k<<<dim3(12, 256, 1), 256>>>(h0, 256, 0, w_hh, 256, 0, b_hh, 0, 1.f,
                                      pgh, 768, 0, BN_, 768, 256, 1.f, 0);
    gru_gate_k<<<BN_, 256>>>(pgx, pgh, h0, hid);

    // node projections (edge-MLP layer-1 factorization); b1 folded into recv half
    gemm_k<<<dim3(4, 256, 1), 256>>>(hid, 256, 0, enc_w1,       512, 0, (const float*)0, 0, 0.f,
                                     peHs, 256, 0, BN_, 256, 256, 1.f, 0);
    gemm_k<<<dim3(4, 256, 1), 256>>>(hid, 256, 0, enc_w1 + 256, 512, 0, enc_b1, 0, 1.f,
                                     peHr, 256, 0, BN_, 256, 256, 1.f, 0);
    gemm_k<<<dim3(4, 256, 1), 256>>>(hid, 256, 0, dec_w1,       512, 0, (const float*)0, 0, 0.f,
                                     pdHs, 256, 0, BN_, 256, 256, 1.f, 0);
    gemm_k<<<dim3(4, 256, 1), 256>>>(hid, 256, 0, dec_w1 + 256, 512, 0, dec_b1, 0, 1.f,
                                     pdHr, 256, 0, BN_, 256, 256, 1.f, 0);

    edge_k<<<Bz, 256>>>(peHs, peHr, pdHs, pdHr, enc_w2, enc_b2, rel, pS);

    // scm_pred = (S @ dec_w2^T + 15*b2) / 15.000001
    gemm_k<<<dim3(3, 256, 1), 256>>>(pS, 256, 0, dec_w2, 256, 0, dec_b2, 0, 15.0f,
                                     scm, 129, 0, BN_, 129, 256, 1.f / 15.000001f, 0);

    // msgs[b,j,k,d] : [16384,128] @ [1024,128]^T + msg_b
    gemm_k<<<dim3(16, 256, 1), 256>>>(obs, 128, 0, msg_w, 128, 0, msg_b, 0, 1.f,
                                      pmsgs, 1024, 0, BN_, 1024, 128, 1.f, 0);

    message_k<<<Bz, 256>>>(rel, pmsgs, obs, pai);

    // per-agent heads (batched over z = agent)
    gemm_k<<<dim3(4, 16, 16), 256>>>(pai, 4096, 256, aw1, 256, 65536, ab1, 256, 1.f,
                                     ph1a, 4096, 256, Bz, 256, 256, 1.f, 1);
    gemm_k<<<dim3(4, 16, 16), 256>>>(pai, 4096, 256, cw1, 256, 65536, cb1, 256, 1.f,
                                     ph1c, 4096, 256, Bz, 256, 256, 1.f, 1);
    gemm_k<<<dim3(1, 16, 16), 256>>>(ph1a, 4096, 256, aw2, 256, 8192, ab2, 32, 1.f,
                                     actor, 512, 32, Bz, 32, 256, 1.f, 0);
    critic2_k<<<BN_ / 8, 256>>>(ph1c, cw2, cb2, critic);
}

// round 3
// speedup vs baseline: 1.9416x; 1.9416x over previous
#include <cuda_runtime.h>
#include <math.h>

#define Bz   1024
#define Nn   16
#define OBS  128
#define ACTD 32
#define RH   256
#define SH   256
#define KK   8
#define Ee   240
#define BN_  (Bz*Nn)   // 16384

// ---------------- scratch (__device__ globals; no allocation) ----------------
__device__ float g_gx  [BN_*768];
__device__ float g_gh  [BN_*768];
__device__ float g_node[BN_*1024];
__device__ float g_S   [BN_*SH];
__device__ float g_msgs[BN_*KK*OBS];
__device__ float g_ai  [BN_*2*OBS];
__device__ float g_h1  [BN_*512];
__device__ float g_pw  [1024*256];
__device__ float g_pb  [1024];
__device__ float g_pw2 [16*512*256];
__device__ float g_pb2 [16*512];
__device__ float g_wih [768*128];
__device__ float g_wihc[768];

// ---------------- tf32 helpers ----------------
__device__ __forceinline__ float tf32r(float x) {
    unsigned u;
    asm("cvt.rna.tf32.f32 %0, %1;" : "=r"(u) : "f"(x));
    return __uint_as_float(u);
}

__device__ __forceinline__ void mma_tf32(float* c, const unsigned* a, const unsigned* b) {
    asm volatile(
        "mma.sync.aligned.m16n8k8.row.col.f32.tf32.tf32.f32 "
        "{%0,%1,%2,%3}, {%4,%5,%6,%7}, {%8,%9}, {%0,%1,%2,%3};"
        : "+f"(c[0]), "+f"(c[1]), "+f"(c[2]), "+f"(c[3])
        : "r"(a[0]), "r"(a[1]), "r"(a[2]), "r"(a[3]), "r"(b[0]), "r"(b[1]));
}

// ---------------- tensor-core tf32 GEMM: C = (A@B^T + bias*biasMul + rowv*colv)*scale [,relu]
// A:[M,K] lda row-major; B:[N,K] ldb row-major; batched over blockIdx.z via strides.
// Requires: M % BM == 0, K % 16 == 0, lda/ldb multiples of 4. N tail handled by guards.
template<int BM, int BN, int WM, int WN>
__global__ void __launch_bounds__((BM/WM)*(BN/WN)*32) gemm_tc(
    const float* __restrict__ A, int lda, long long sA,
    const float* __restrict__ B, int ldb, long long sB,
    const float* __restrict__ bias, long long sBias, float biasMul,
    const float* __restrict__ rowv, const float* __restrict__ colv, int cvs,
    float* __restrict__ C, int ldc, long long sC,
    int M, int N, int K, float scale, int relu)
{
    constexpr int BK = 16;
    constexpr int WARPS_M = BM / WM;
    constexpr int WARPS_N = BN / WN;
    constexpr int NWARP = WARPS_M * WARPS_N;
    constexpr int NT = NWARP * 32;
    constexpr int MT = WM / 16;
    constexpr int NTf = WN / 8;
    constexpr int SA = BM + 8;
    constexpr int SB = BN + 8;

    __shared__ float As[BK][SA];
    __shared__ float Bs[BK][SB];

    int bz = blockIdx.z;
    A += (long long)bz * sA;
    B += (long long)bz * sB;
    C += (long long)bz * sC;
    const float* bp = bias ? bias + (long long)bz * sBias : (const float*)0;

    int t = threadIdx.x;
    int wid = t >> 5, lane = t & 31;
    int wm0 = (wid % WARPS_M) * WM;
    int wn0 = (wid / WARPS_M) * WN;
    int row0 = blockIdx.y * BM;
    int col0 = blockIdx.x * BN;
    int kr = lane & 3, mrow = lane >> 2;

    float acc[MT * NTf * 4];
    #pragma unroll
    for (int i = 0; i < MT * NTf * 4; i++) acc[i] = 0.f;

    constexpr int AQ = (BM * BK) / (NT * 4);
    constexpr int BQ = (BN * BK) / (NT * 4);

    for (int k0 = 0; k0 < K; k0 += BK) {
        #pragma unroll
        for (int q = 0; q < AQ; q++) {
            int i = q * NT + t;
            int r = i >> 2, ks = (i & 3) * 4;
            const float4 v = *(const float4*)(A + (long long)(row0 + r) * lda + k0 + ks);
            As[ks + 0][r] = tf32r(v.x);
            As[ks + 1][r] = tf32r(v.y);
            As[ks + 2][r] = tf32r(v.z);
            As[ks + 3][r] = tf32r(v.w);
        }
        #pragma unroll
        for (int q = 0; q < BQ; q++) {
            int i = q * NT + t;
            int r = i >> 2, ks = (i & 3) * 4;
            int gc = col0 + r;
            float4 v = make_float4(0.f, 0.f, 0.f, 0.f);
            if (gc < N) v = *(const float4*)(B + (long long)gc * ldb + k0 + ks);
            Bs[ks + 0][r] = tf32r(v.x);
            Bs[ks + 1][r] = tf32r(v.y);
            Bs[ks + 2][r] = tf32r(v.z);
            Bs[ks + 3][r] = tf32r(v.w);
        }
        __syncthreads();

        #pragma unroll
        for (int s = 0; s < 2; s++) {
            int ks = s * 8;
            unsigned afr[MT][4], bfr[NTf][2];
            #pragma unroll
            for (int mt = 0; mt < MT; mt++) {
                int m = wm0 + mt * 16 + mrow;
                afr[mt][0] = __float_as_uint(As[ks + kr][m]);
                afr[mt][1] = __float_as_uint(As[ks + kr][m + 8]);
                afr[mt][2] = __float_as_uint(As[ks + kr + 4][m]);
                afr[mt][3] = __float_as_uint(As[ks + kr + 4][m + 8]);
            }
            #pragma unroll
            for (int nt = 0; nt < NTf; nt++) {
                int n = wn0 + nt * 8 + mrow;
                bfr[nt][0] = __float_as_uint(Bs[ks + kr][n]);
                bfr[nt][1] = __float_as_uint(Bs[ks + kr + 4][n]);
            }
            #pragma unroll
            for (int mt = 0; mt < MT; mt++)
                #pragma unroll
                for (int nt = 0; nt < NTf; nt++)
                    mma_tf32(&acc[(mt * NTf + nt) * 4], afr[mt], bfr[nt]);
        }
        __syncthreads();
    }

    #pragma unroll
    for (int mt = 0; mt < MT; mt++) {
        int r0 = row0 + wm0 + mt * 16 + mrow;
        #pragma unroll
        for (int nt = 0; nt < NTf; nt++) {
            int cbase = col0 + wn0 + nt * 8 + 2 * kr;
            const float* cc = &acc[(mt * NTf + nt) * 4];
            #pragma unroll
            for (int h = 0; h < 2; h++) {
                int gr = r0 + h * 8;
                #pragma unroll
                for (int w2 = 0; w2 < 2; w2++) {
                    int gc = cbase + w2;
                    if (gc < N) {
                        float v = cc[h * 2 + w2];
                        if (bp) v += bp[gc] * biasMul;
                        if (rowv) v += rowv[gr] * colv[(long long)gc * cvs];
                        v *= scale;
                        if (relu) v = fmaxf(v, 0.f);
                        C[(long long)gr * ldc + gc] = v;
                    }
                }
            }
        }
    }
}

// ---------------- pack w_ih [768,129] -> aligned [768,128] + column 128 ----------------
__global__ void pack_wih_k(const float* __restrict__ w_ih,
                           float* __restrict__ wp, float* __restrict__ wc)
{
    int idx = blockIdx.x * 256 + threadIdx.x;
    if (idx < 768 * 128) {
        int r = idx >> 7, c = idx & 127;
        wp[idx] = w_ih[r * 129 + c];
    }
    if (idx < 768) wc[idx] = w_ih[idx * 129 + 128];
}

// ---------------- pack node-projection weights: pw [1024,256], pb[1024] ----------------
__global__ void pack_node_k(const float* __restrict__ ew1, const float* __restrict__ eb1,
                            const float* __restrict__ dw1, const float* __restrict__ db1,
                            float* __restrict__ pw, float* __restrict__ pb)
{
    int idx = blockIdx.x * 256 + threadIdx.x;
    if (idx < 1024 * 256) {
        int r = idx >> 8, c = idx & 255;
        float v;
        if (r < 256)      v = ew1[r * 512 + c];
        else if (r < 512) v = ew1[(r - 256) * 512 + 256 + c];
        else if (r < 768) v = dw1[(r - 512) * 512 + c];
        else              v = dw1[(r - 768) * 512 + 256 + c];
        pw[idx] = v;
    }
    if (idx < 1024) {
        int r = idx;
        float v = 0.f;
        if (r >= 256 && r < 512) v = eb1[r - 256];
        else if (r >= 768)       v = db1[r - 768];
        pb[r] = v;
    }
}

// ---------------- pack head layer-1 weights: pw2 [16,512,256], pb2[16,512] ----------------
__global__ void pack_head_k(const float* __restrict__ aw1, const float* __restrict__ ab1,
                            const float* __restrict__ cw1, const float* __restrict__ cb1,
                            float* __restrict__ pw2, float* __restrict__ pb2)
{
    int idx = blockIdx.x * 256 + threadIdx.x;
    if (idx < 16 * 512 * 256) {
        int n = idx >> 17;
        int r = (idx >> 8) & 511;
        int c = idx & 255;
        float v = (r < 256) ? aw1[n * 65536 + r * 256 + c]
                            : cw1[n * 65536 + (r - 256) * 256 + c];
        pw2[idx] = v;
    }
    if (idx < 16 * 512) {
        int n = idx >> 9, r = idx & 511;
        pb2[idx] = (r < 256) ? ab1[n * 256 + r] : cb1[n * 256 + r - 256];
    }
}

// ---------------- GRU gates (float4) ----------------
__global__ void gru_gate4_k(const float* __restrict__ gx, const float* __restrict__ gh,
                            const float* __restrict__ h0, float* __restrict__ h)
{
    int idx = blockIdx.x * blockDim.x + threadIdx.x;  // over BN_*64
    if (idx >= BN_ * 64) return;
    int m = idx >> 6;
    int c4 = (idx & 63) * 4;
    long long bx = (long long)m * 768 + c4;
    float4 xr = *(const float4*)(gx + bx);
    float4 xz = *(const float4*)(gx + bx + 256);
    float4 xn = *(const float4*)(gx + bx + 512);
    float4 hr = *(const float4*)(gh + bx);
    float4 hz = *(const float4*)(gh + bx + 256);
    float4 hn = *(const float4*)(gh + bx + 512);
    float4 h0v = *(const float4*)(h0 + (long long)m * 256 + c4);
    float4 o;
    {
        float r = 1.f / (1.f + expf(-(xr.x + hr.x)));
        float z = 1.f / (1.f + expf(-(xz.x + hz.x)));
        float nc = tanhf(xn.x + r * hn.x);
        o.x = (1.f - z) * nc + z * h0v.x;
    }
    {
        float r = 1.f / (1.f + expf(-(xr.y + hr.y)));
        float z = 1.f / (1.f + expf(-(xz.y + hz.y)));
        float nc = tanhf(xn.y + r * hn.y);
        o.y = (1.f - z) * nc + z * h0v.y;
    }
    {
        float r = 1.f / (1.f + expf(-(xr.z + hr.z)));
        float z = 1.f / (1.f + expf(-(xz.z + hz.z)));
        float nc = tanhf(xn.z + r * hn.z);
        o.z = (1.f - z) * nc + z * h0v.z;
    }
    {
        float r = 1.f / (1.f + expf(-(xr.w + hr.w)));
        float z = 1.f / (1.f + expf(-(xz.w + hz.w)));
        float nc = tanhf(xn.w + r * hn.w);
        o.w = (1.f - z) * nc + z * h0v.w;
    }
    *(float4*)(h + (long long)m * 256 + c4) = o;
}

// ---------------- fused per-batch edge kernel (reads packed node projections) ----------------
__global__ __launch_bounds__(256) void edge_k(
    const float* __restrict__ node,          // [B*N, 1024]: eHs|eHr|dHs|dHr
    const float* __restrict__ w2, const float* __restrict__ b2,
    float* __restrict__ rel, float* __restrict__ Sout)
{
    __shared__ float sW2[KK * SH];
    __shared__ float sS[Nn][SH];
    int b = blockIdx.x;
    int tid = threadIdx.x;
    for (int i = tid; i < KK * SH; i += 256) sW2[i] = w2[i];
    for (int i = tid; i < Nn * SH; i += 256) (&sS[0][0])[i] = 0.f;
    __syncthreads();

    int w = tid >> 5, lane = tid & 31;
    long long base = (long long)b * Nn * 1024;
    for (int ii = 0; ii < 2; ii++) {
        int i = w * 2 + ii;
        float eR[8], dR[8];
        #pragma unroll
        for (int q = 0; q < 8; q++) {
            int c = lane + 32 * q;
            eR[q] = node[base + i * 1024 + 256 + c];
            dR[q] = node[base + i * 1024 + 768 + c];
        }
        for (int j = 0; j < Nn; j++) {
            if (j == i) continue;
            float part[KK];
            #pragma unroll
            for (int k = 0; k < KK; k++) part[k] = 0.f;
            #pragma unroll
            for (int q = 0; q < 8; q++) {
                int c = lane + 32 * q;
                float pe = node[base + j * 1024 + c] + eR[q];
                pe = fmaxf(pe, 0.f);
                #pragma unroll
                for (int k = 0; k < KK; k++) part[k] += pe * sW2[k * SH + c];
                float pd = node[base + j * 1024 + 512 + c] + dR[q];
                pd = fmaxf(pd, 0.f);
                sS[i][c] += pd;
            }
            #pragma unroll
            for (int k = 0; k < KK; k++) {
                #pragma unroll
                for (int off = 16; off; off >>= 1)
                    part[k] += __shfl_xor_sync(0xffffffffu, part[k], off);
                part[k] += b2[k];
            }
            if (lane == 0) {
                float mx = part[0];
                #pragma unroll
                for (int k = 1; k < KK; k++) mx = fmaxf(mx, part[k]);
                float e_[KK], s = 0.f;
                #pragma unroll
                for (int k = 0; k < KK; k++) { e_[k] = expf(part[k] - mx); s += e_[k]; }
                float inv = 1.f / s;
                int jj = (j < i) ? j : j - 1;
                long long eo = ((long long)b * Ee + i * 15 + jj) * KK;
                #pragma unroll
                for (int k = 0; k < KK; k++) rel[eo + k] = e_[k] * inv;
            }
        }
    }
    __syncthreads();
    long long sb = (long long)b * Nn * SH;
    for (int i = tid; i < Nn * SH; i += 256)
        Sout[sb + i] = (&sS[0][0])[i];
}

// ---------------- message aggregation + build ai = [obs, message] ----------------
__global__ __launch_bounds__(256) void message_k(
    const float* __restrict__ rel, const float* __restrict__ msgs,
    const float* __restrict__ obs, float* __restrict__ ai)
{
    __shared__ float sRel[Ee * KK];  // 1920
    int b = blockIdx.x;
    int tid = threadIdx.x;
    for (int i = tid; i < Ee * KK; i += 256) sRel[i] = rel[(long long)b * Ee * KK + i];
    __syncthreads();

    int d = tid & 127;
    int g = tid >> 7;
    float acc[8];
    #pragma unroll
    for (int ii = 0; ii < 8; ii++) acc[ii] = 0.f;
    long long mb = (long long)b * Nn * KK * OBS;
    for (int j = 0; j < Nn; j++) {
        float mj[KK];
        #pragma unroll
        for (int k = 0; k < KK; k++) mj[k] = msgs[mb + (j * KK + k) * OBS + d];
        #pragma unroll
        for (int ii = 0; ii < 8; ii++) {
            int i = g * 8 + ii;
            if (i == j) continue;
            int jj = (j < i) ? j : j - 1;
            const float* r = &sRel[(i * 15 + jj) * KK];
            float a = acc[ii];
            #pragma unroll
            for (int k = 0; k < KK; k++) a += r[k] * mj[k];
            acc[ii] = a;
        }
    }
    long long ab = (long long)b * Nn * 2 * OBS;
    #pragma unroll
    for (int ii = 0; ii < 8; ii++) {
        int i = g * 8 + ii;
        ai[ab + i * 2 * OBS + OBS + d] = acc[ii];
    }
    for (int idx = tid; idx < Nn * OBS; idx += 256) {
        int i = idx >> 7, dd = idx & 127;
        ai[ab + i * 2 * OBS + dd] = obs[(long long)b * Nn * OBS + idx];
    }
}

// ---------------- critic layer 2 (N=1): one warp per (b,n) dot ----------------
__global__ void critic2_k(const float* __restrict__ h1, const float* __restrict__ w2,
                          const float* __restrict__ b2v, float* __restrict__ out)
{
    int w = (blockIdx.x * blockDim.x + threadIdx.x) >> 5;
    int lane = threadIdx.x & 31;
    if (w >= BN_) return;
    int n = w & 15;
    float s = 0.f;
    #pragma unroll
    for (int q = 0; q < 8; q++) {
        int c = lane + 32 * q;
        s += h1[(long long)w * 512 + 256 + c] * w2[n * 256 + c];
    }
    #pragma unroll
    for (int off = 16; off; off >>= 1) s += __shfl_xor_sync(0xffffffffu, s, off);
    if (lane == 0) out[w] = s + b2v[n];
}

// ---------------- launch ----------------
extern "C" void kernel_launch(void* const* d_in, const int* in_sizes, int n_in,
                              void* d_out, int out_size)
{
    const float* obs    = (const float*)d_in[0];
    const float* rew    = (const float*)d_in[1];
    const float* h0     = (const float*)d_in[2];
    const float* w_ih   = (const float*)d_in[3];
    const float* w_hh   = (const float*)d_in[4];
    const float* b_ih   = (const float*)d_in[5];
    const float* b_hh   = (const float*)d_in[6];
    const float* enc_w1 = (const float*)d_in[7];
    const float* enc_b1 = (const float*)d_in[8];
    const float* enc_w2 = (const float*)d_in[9];
    const float* enc_b2 = (const float*)d_in[10];
    const float* dec_w1 = (const float*)d_in[11];
    const float* dec_b1 = (const float*)d_in[12];
    const float* dec_w2 = (const float*)d_in[13];
    const float* dec_b2 = (const float*)d_in[14];
    const float* msg_w  = (const float*)d_in[15];
    const float* msg_b  = (const float*)d_in[16];
    const float* aw1    = (const float*)d_in[17];
    const float* ab1    = (const float*)d_in[18];
    const float* aw2    = (const float*)d_in[19];
    const float* ab2    = (const float*)d_in[20];
    const float* cw1    = (const float*)d_in[21];
    const float* cb1    = (const float*)d_in[22];
    const float* cw2    = (const float*)d_in[23];
    const float* cb2    = (const float*)d_in[24];
    float* out = (float*)d_out;

    float *pgx, *pgh, *pnode, *pS, *pmsgs, *pai, *ph1, *pw, *pb, *pw2, *pb2, *pwih, *pwihc;
    cudaGetSymbolAddress((void**)&pgx,   g_gx);
    cudaGetSymbolAddress((void**)&pgh,   g_gh);
    cudaGetSymbolAddress((void**)&pnode, g_node);
    cudaGetSymbolAddress((void**)&pS,    g_S);
    cudaGetSymbolAddress((void**)&pmsgs, g_msgs);
    cudaGetSymbolAddress((void**)&pai,   g_ai);
    cudaGetSymbolAddress((void**)&ph1,   g_h1);
    cudaGetSymbolAddress((void**)&pw,    g_pw);
    cudaGetSymbolAddress((void**)&pb,    g_pb);
    cudaGetSymbolAddress((void**)&pw2,   g_pw2);
    cudaGetSymbolAddress((void**)&pb2,   g_pb2);
    cudaGetSymbolAddress((void**)&pwih,  g_wih);
    cudaGetSymbolAddress((void**)&pwihc, g_wihc);

    float* actor  = out;                 // [B,N,32]    524288
    float* critic = out + 524288;        // [B,N,1]     16384
    float* scm    = out + 540672;        // [B,N,129]   2113536
    float* rel    = out + 2654208;       // [B,E,8]     1966080
    float* hid    = out + 4620288;       // [1,B*N,256] 4194304

    const float* NUL = (const float*)0;

    // weight packing (small)
    pack_wih_k<<<(768 * 128 + 255) / 256, 256>>>(w_ih, pwih, pwihc);
    pack_node_k<<<1024, 256>>>(enc_w1, enc_b1, dec_w1, dec_b1, pw, pb);
    pack_head_k<<<(16 * 512 * 256 + 255) / 256, 256>>>(aw1, ab1, cw1, cb1, pw2, pb2);

    // GRU: gx = obs @ Wih[:, :128]^T + rew*Wih[:,128] + b_ih ; gh = h0 @ Whh^T + b_hh
    gemm_tc<128,128,64,64><<<dim3(6, 128, 1), 128>>>(
        obs, 128, 0, pwih, 128, 0, b_ih, 0, 1.f, rew, pwihc, 1,
        pgx, 768, 0, BN_, 768, 128, 1.f, 0);
    gemm_tc<128,128,64,64><<<dim3(6, 128, 1), 128>>>(
        h0, 256, 0, w_hh, 256, 0, b_hh, 0, 1.f, NUL, NUL, 0,
        pgh, 768, 0, BN_, 768, 256, 1.f, 0);
    gru_gate4_k<<<(BN_ * 64 + 255) / 256, 256>>>(pgx, pgh, h0, hid);

    // packed node projections: [16384,1024] = hid @ pw^T + pb
    gemm_tc<128,128,64,64><<<dim3(8, 128, 1), 128>>>(
        hid, 256, 0, pw, 256, 0, pb, 0, 1.f, NUL, NUL, 0,
        pnode, 1024, 0, BN_, 1024, 256, 1.f, 0);

    edge_k<<<Bz, 256>>>(pnode, enc_w2, enc_b2, rel, pS);

    // scm_pred = (S @ dec_w2^T + 15*b2) / 15.000001
    gemm_tc<128,128,64,64><<<dim3(2, 128, 1), 128>>>(
        pS, 256, 0, dec_w2, 256, 0, dec_b2, 0, 15.0f, NUL, NUL, 0,
        scm, 129, 0, BN_, 129, 256, 1.f / 15.000001f, 0);

    // msgs: [16384,1024] = obs @ msg_w^T + msg_b
    gemm_tc<128,128,64,64><<<dim3(8, 128, 1), 128>>>(
        obs, 128, 0, msg_w, 128, 0, msg_b, 0, 1.f, NUL, NUL, 0,
        pmsgs, 1024, 0, BN_, 1024, 128, 1.f, 0);

    message_k<<<Bz, 256>>>(rel, pmsgs, obs, pai);

    // fused actor+critic layer 1, batched over agent: [1024,512] per agent
    gemm_tc<128,128,64,64><<<dim3(4, 8, 16), 128>>>(
        pai, 4096, 256, pw2, 256, 512 * 256, pb2, 512, 1.f, NUL, NUL, 0,
        ph1, 8192, 512, Bz, 512, 256, 1.f, 1);

    // actor layer 2 (N=32), batched over agent
    gemm_tc<128,32,32,32><<<dim3(1, 8, 16), 128>>>(
        ph1, 8192, 512, aw2, 256, 32 * 256, ab2, 32, 1.f, NUL, NUL, 0,
        actor, 512, 32, Bz, 32, 256, 1.f, 0);

    critic2_k<<<BN_ / 8, 256>>>(ph1, cw2, cb2, critic);
}

// round 4
// speedup vs baseline: 2.2842x; 1.1764x over previous
#include <cuda_runtime.h>
#include <math.h>

#define Bz   1024
#define Nn   16
#define OBS  128
#define ACTD 32
#define RH   256
#define SH   256
#define KK   8
#define Ee   240
#define BN_  (Bz*Nn)   // 16384

// ---------------- scratch (__device__ globals; no allocation) ----------------
__device__ float g_gx  [BN_*768];
__device__ float g_gh  [BN_*768];
__device__ float g_node[BN_*1024];
__device__ float g_S   [BN_*SH];
__device__ float g_msgs[BN_*KK*OBS];
__device__ float g_ai  [BN_*2*OBS];
__device__ float g_h1  [BN_*512];
__device__ float g_pw  [1024*256];
__device__ float g_pb  [1024];
__device__ float g_pw2 [16*512*256];
__device__ float g_pb2 [16*512];
__device__ float g_wih [768*128];
__device__ float g_wihc[768];

// ---------------- tf32 helpers ----------------
__device__ __forceinline__ float tf32r(float x) {
    unsigned u;
    asm("cvt.rna.tf32.f32 %0, %1;" : "=r"(u) : "f"(x));
    return __uint_as_float(u);
}

__device__ __forceinline__ void mma_tf32(float* c, const unsigned* a, const unsigned* b) {
    asm volatile(
        "mma.sync.aligned.m16n8k8.row.col.f32.tf32.tf32.f32 "
        "{%0,%1,%2,%3}, {%4,%5,%6,%7}, {%8,%9}, {%0,%1,%2,%3};"
        : "+f"(c[0]), "+f"(c[1]), "+f"(c[2]), "+f"(c[3])
        : "r"(a[0]), "r"(a[1]), "r"(a[2]), "r"(a[3]), "r"(b[0]), "r"(b[1]));
}

// ---------------- tensor-core tf32 GEMM (double-buffered, register prefetch)
// C = (A@B^T + bias*biasMul + rowv*colv)*scale [,relu]
// A:[M,K] lda row-major; B:[N,K] ldb row-major; batched over blockIdx.z via strides.
// Requires: M % BM == 0, K % 16 == 0, lda/ldb multiples of 4.
template<int BM, int BN, int WM, int WN>
__global__ void __launch_bounds__((BM/WM)*(BN/WN)*32, ((BM/WM)*(BN/WN) == 8) ? 2 : 1)
gemm_tc(
    const float* __restrict__ A, int lda, long long sA,
    const float* __restrict__ B, int ldb, long long sB,
    const float* __restrict__ bias, long long sBias, float biasMul,
    const float* __restrict__ rowv, const float* __restrict__ colv, int cvs,
    float* __restrict__ C, int ldc, long long sC,
    int M, int N, int K, float scale, int relu)
{
    constexpr int BK = 16;
    constexpr int WARPS_M = BM / WM;
    constexpr int WARPS_N = BN / WN;
    constexpr int NWARP = WARPS_M * WARPS_N;
    constexpr int NT = NWARP * 32;
    constexpr int MT = WM / 16;
    constexpr int NTf = WN / 8;
    constexpr int SA = BM + 8;   // stride mod 32 == 8 -> conflict-free frag loads
    constexpr int SB = BN + 8;
    constexpr int AQ = (BM * BK) / (NT * 4);
    constexpr int BQ = (BN * BK) / (NT * 4);

    __shared__ float As[2][BK][SA];
    __shared__ float Bs[2][BK][SB];

    int bz = blockIdx.z;
    A += (long long)bz * sA;
    B += (long long)bz * sB;
    C += (long long)bz * sC;
    const float* bp = bias ? bias + (long long)bz * sBias : (const float*)0;

    int t = threadIdx.x;
    int wid = t >> 5, lane = t & 31;
    int wm0 = (wid % WARPS_M) * WM;
    int wn0 = (wid / WARPS_M) * WN;
    int row0 = blockIdx.y * BM;
    int col0 = blockIdx.x * BN;
    int kr = lane & 3, mrow = lane >> 2;

    float acc[MT * NTf * 4];
    #pragma unroll
    for (int i = 0; i < MT * NTf * 4; i++) acc[i] = 0.f;

    float4 ra[AQ], rbv[BQ];

    // ---- prologue: stage k0 = 0 into buffer 0 ----
    #pragma unroll
    for (int q = 0; q < AQ; q++) {
        int i = q * NT + t;
        int r = i >> 2, ks = (i & 3) * 4;
        ra[q] = *(const float4*)(A + (long long)(row0 + r) * lda + ks);
    }
    #pragma unroll
    for (int q = 0; q < BQ; q++) {
        int i = q * NT + t;
        int r = i >> 2, ks = (i & 3) * 4;
        int gc = col0 + r;
        rbv[q] = make_float4(0.f, 0.f, 0.f, 0.f);
        if (gc < N) rbv[q] = *(const float4*)(B + (long long)gc * ldb + ks);
    }
    #pragma unroll
    for (int q = 0; q < AQ; q++) {
        int i = q * NT + t;
        int r = i >> 2, ks = (i & 3) * 4;
        As[0][ks + 0][r] = tf32r(ra[q].x);
        As[0][ks + 1][r] = tf32r(ra[q].y);
        As[0][ks + 2][r] = tf32r(ra[q].z);
        As[0][ks + 3][r] = tf32r(ra[q].w);
    }
    #pragma unroll
    for (int q = 0; q < BQ; q++) {
        int i = q * NT + t;
        int r = i >> 2, ks = (i & 3) * 4;
        Bs[0][ks + 0][r] = tf32r(rbv[q].x);
        Bs[0][ks + 1][r] = tf32r(rbv[q].y);
        Bs[0][ks + 2][r] = tf32r(rbv[q].z);
        Bs[0][ks + 3][r] = tf32r(rbv[q].w);
    }
    __syncthreads();

    int buf = 0;
    for (int k0 = 0; k0 < K; k0 += BK) {
        bool next = (k0 + BK) < K;
        // prefetch next tile into registers (overlaps with MMA below)
        if (next) {
            int kn = k0 + BK;
            #pragma unroll
            for (int q = 0; q < AQ; q++) {
                int i = q * NT + t;
                int r = i >> 2, ks = (i & 3) * 4;
                ra[q] = *(const float4*)(A + (long long)(row0 + r) * lda + kn + ks);
            }
            #pragma unroll
            for (int q = 0; q < BQ; q++) {
                int i = q * NT + t;
                int r = i >> 2, ks = (i & 3) * 4;
                int gc = col0 + r;
                rbv[q] = make_float4(0.f, 0.f, 0.f, 0.f);
                if (gc < N) rbv[q] = *(const float4*)(B + (long long)gc * ldb + kn + ks);
            }
        }

        // compute current buffer
        #pragma unroll
        for (int s = 0; s < 2; s++) {
            int ks = s * 8;
            unsigned afr[MT][4], bfr[NTf][2];
            #pragma unroll
            for (int mt = 0; mt < MT; mt++) {
                int m = wm0 + mt * 16 + mrow;
                afr[mt][0] = __float_as_uint(As[buf][ks + kr][m]);
                afr[mt][1] = __float_as_uint(As[buf][ks + kr][m + 8]);
                afr[mt][2] = __float_as_uint(As[buf][ks + kr + 4][m]);
                afr[mt][3] = __float_as_uint(As[buf][ks + kr + 4][m + 8]);
            }
            #pragma unroll
            for (int nt = 0; nt < NTf; nt++) {
                int n = wn0 + nt * 8 + mrow;
                bfr[nt][0] = __float_as_uint(Bs[buf][ks + kr][n]);
                bfr[nt][1] = __float_as_uint(Bs[buf][ks + kr + 4][n]);
            }
            #pragma unroll
            for (int mt = 0; mt < MT; mt++)
                #pragma unroll
                for (int nt = 0; nt < NTf; nt++)
                    mma_tf32(&acc[(mt * NTf + nt) * 4], afr[mt], bfr[nt]);
        }

        // store prefetched tile into the other buffer
        if (next) {
            int nb = buf ^ 1;
            #pragma unroll
            for (int q = 0; q < AQ; q++) {
                int i = q * NT + t;
                int r = i >> 2, ks = (i & 3) * 4;
                As[nb][ks + 0][r] = tf32r(ra[q].x);
                As[nb][ks + 1][r] = tf32r(ra[q].y);
                As[nb][ks + 2][r] = tf32r(ra[q].z);
                As[nb][ks + 3][r] = tf32r(ra[q].w);
            }
            #pragma unroll
            for (int q = 0; q < BQ; q++) {
                int i = q * NT + t;
                int r = i >> 2, ks = (i & 3) * 4;
                Bs[nb][ks + 0][r] = tf32r(rbv[q].x);
                Bs[nb][ks + 1][r] = tf32r(rbv[q].y);
                Bs[nb][ks + 2][r] = tf32r(rbv[q].z);
                Bs[nb][ks + 3][r] = tf32r(rbv[q].w);
            }
        }
        __syncthreads();
        buf ^= 1;
    }

    // ---- epilogue ----
    #pragma unroll
    for (int mt = 0; mt < MT; mt++) {
        int r0 = row0 + wm0 + mt * 16 + mrow;
        #pragma unroll
        for (int nt = 0; nt < NTf; nt++) {
            int cbase = col0 + wn0 + nt * 8 + 2 * kr;
            const float* cc = &acc[(mt * NTf + nt) * 4];
            #pragma unroll
            for (int h = 0; h < 2; h++) {
                int gr = r0 + h * 8;
                #pragma unroll
                for (int w2 = 0; w2 < 2; w2++) {
                    int gc = cbase + w2;
                    if (gc < N) {
                        float v = cc[h * 2 + w2];
                        if (bp) v += bp[gc] * biasMul;
                        if (rowv) v += rowv[gr] * colv[(long long)gc * cvs];
                        v *= scale;
                        if (relu) v = fmaxf(v, 0.f);
                        C[(long long)gr * ldc + gc] = v;
                    }
                }
            }
        }
    }
}

// ---------------- pack w_ih [768,129] -> aligned [768,128] + column 128 ----------------
__global__ void pack_wih_k(const float* __restrict__ w_ih,
                           float* __restrict__ wp, float* __restrict__ wc)
{
    int idx = blockIdx.x * 256 + threadIdx.x;
    if (idx < 768 * 128) {
        int r = idx >> 7, c = idx & 127;
        wp[idx] = w_ih[r * 129 + c];
    }
    if (idx < 768) wc[idx] = w_ih[idx * 129 + 128];
}

// ---------------- pack node-projection weights: pw [1024,256], pb[1024] ----------------
__global__ void pack_node_k(const float* __restrict__ ew1, const float* __restrict__ eb1,
                            const float* __restrict__ dw1, const float* __restrict__ db1,
                            float* __restrict__ pw, float* __restrict__ pb)
{
    int idx = blockIdx.x * 256 + threadIdx.x;
    if (idx < 1024 * 256) {
        int r = idx >> 8, c = idx & 255;
        float v;
        if (r < 256)      v = ew1[r * 512 + c];
        else if (r < 512) v = ew1[(r - 256) * 512 + 256 + c];
        else if (r < 768) v = dw1[(r - 512) * 512 + c];
        else              v = dw1[(r - 768) * 512 + 256 + c];
        pw[idx] = v;
    }
    if (idx < 1024) {
        int r = idx;
        float v = 0.f;
        if (r >= 256 && r < 512) v = eb1[r - 256];
        else if (r >= 768)       v = db1[r - 768];
        pb[r] = v;
    }
}

// ---------------- pack head layer-1 weights: pw2 [16,512,256], pb2[16,512] ----------------
__global__ void pack_head_k(const float* __restrict__ aw1, const float* __restrict__ ab1,
                            const float* __restrict__ cw1, const float* __restrict__ cb1,
                            float* __restrict__ pw2, float* __restrict__ pb2)
{
    int idx = blockIdx.x * 256 + threadIdx.x;
    if (idx < 16 * 512 * 256) {
        int n = idx >> 17;
        int r = (idx >> 8) & 511;
        int c = idx & 255;
        float v = (r < 256) ? aw1[n * 65536 + r * 256 + c]
                            : cw1[n * 65536 + (r - 256) * 256 + c];
        pw2[idx] = v;
    }
    if (idx < 16 * 512) {
        int n = idx >> 9, r = idx & 511;
        pb2[idx] = (r < 256) ? ab1[n * 256 + r] : cb1[n * 256 + r - 256];
    }
}

// ---------------- GRU gates (float4) ----------------
__global__ void gru_gate4_k(const float* __restrict__ gx, const float* __restrict__ gh,
                            const float* __restrict__ h0, float* __restrict__ h)
{
    int idx = blockIdx.x * blockDim.x + threadIdx.x;  // over BN_*64
    if (idx >= BN_ * 64) return;
    int m = idx >> 6;
    int c4 = (idx & 63) * 4;
    long long bx = (long long)m * 768 + c4;
    float4 xr = *(const float4*)(gx + bx);
    float4 xz = *(const float4*)(gx + bx + 256);
    float4 xn = *(const float4*)(gx + bx + 512);
    float4 hr = *(const float4*)(gh + bx);
    float4 hz = *(const float4*)(gh + bx + 256);
    float4 hn = *(const float4*)(gh + bx + 512);
    float4 h0v = *(const float4*)(h0 + (long long)m * 256 + c4);
    float4 o;
    {
        float r = 1.f / (1.f + expf(-(xr.x + hr.x)));
        float z = 1.f / (1.f + expf(-(xz.x + hz.x)));
        float nc = tanhf(xn.x + r * hn.x);
        o.x = (1.f - z) * nc + z * h0v.x;
    }
    {
        float r = 1.f / (1.f + expf(-(xr.y + hr.y)));
        float z = 1.f / (1.f + expf(-(xz.y + hz.y)));
        float nc = tanhf(xn.y + r * hn.y);
        o.y = (1.f - z) * nc + z * h0v.y;
    }
    {
        float r = 1.f / (1.f + expf(-(xr.z + hr.z)));
        float z = 1.f / (1.f + expf(-(xz.z + hz.z)));
        float nc = tanhf(xn.z + r * hn.z);
        o.z = (1.f - z) * nc + z * h0v.z;
    }
    {
        float r = 1.f / (1.f + expf(-(xr.w + hr.w)));
        float z = 1.f / (1.f + expf(-(xz.w + hz.w)));
        float nc = tanhf(xn.w + r * hn.w);
        o.w = (1.f - z) * nc + z * h0v.w;
    }
    *(float4*)(h + (long long)m * 256 + c4) = o;
}

// ---------------- fused per-batch edge kernel (reads packed node projections) ----------------
__global__ __launch_bounds__(256) void edge_k(
    const float* __restrict__ node,          // [B*N, 1024]: eHs|eHr|dHs|dHr
    const float* __restrict__ w2, const float* __restrict__ b2,
    float* __restrict__ rel, float* __restrict__ Sout)
{
    __shared__ float sW2[KK * SH];
    __shared__ float sS[Nn][SH];
    int b = blockIdx.x;
    int tid = threadIdx.x;
    for (int i = tid; i < KK * SH; i += 256) sW2[i] = w2[i];
    for (int i = tid; i < Nn * SH; i += 256) (&sS[0][0])[i] = 0.f;
    __syncthreads();

    int w = tid >> 5, lane = tid & 31;
    long long base = (long long)b * Nn * 1024;
    for (int ii = 0; ii < 2; ii++) {
        int i = w * 2 + ii;
        float eR[8], dR[8];
        #pragma unroll
        for (int q = 0; q < 8; q++) {
            int c = lane + 32 * q;
            eR[q] = node[base + i * 1024 + 256 + c];
            dR[q] = node[base + i * 1024 + 768 + c];
        }
        for (int j = 0; j < Nn; j++) {
            if (j == i) continue;
            float part[KK];
            #pragma unroll
            for (int k = 0; k < KK; k++) part[k] = 0.f;
            #pragma unroll
            for (int q = 0; q < 8; q++) {
                int c = lane + 32 * q;
                float pe = node[base + j * 1024 + c] + eR[q];
                pe = fmaxf(pe, 0.f);
                #pragma unroll
                for (int k = 0; k < KK; k++) part[k] += pe * sW2[k * SH + c];
                float pd = node[base + j * 1024 + 512 + c] + dR[q];
                pd = fmaxf(pd, 0.f);
                sS[i][c] += pd;
            }
            #pragma unroll
            for (int k = 0; k < KK; k++) {
                #pragma unroll
                for (int off = 16; off; off >>= 1)
                    part[k] += __shfl_xor_sync(0xffffffffu, part[k], off);
                part[k] += b2[k];
            }
            if (lane == 0) {
                float mx = part[0];
                #pragma unroll
                for (int k = 1; k < KK; k++) mx = fmaxf(mx, part[k]);
                float e_[KK], s = 0.f;
                #pragma unroll
                for (int k = 0; k < KK; k++) { e_[k] = expf(part[k] - mx); s += e_[k]; }
                float inv = 1.f / s;
                int jj = (j < i) ? j : j - 1;
                long long eo = ((long long)b * Ee + i * 15 + jj) * KK;
                #pragma unroll
                for (int k = 0; k < KK; k++) rel[eo + k] = e_[k] * inv;
            }
        }
    }
    __syncthreads();
    long long sb = (long long)b * Nn * SH;
    for (int i = tid; i < Nn * SH; i += 256)
        Sout[sb + i] = (&sS[0][0])[i];
}

// ---------------- message aggregation + build ai = [obs, message] ----------------
__global__ __launch_bounds__(256) void message_k(
    const float* __restrict__ rel, const float* __restrict__ msgs,
    const float* __restrict__ obs, float* __restrict__ ai)
{
    __shared__ float sRel[Ee * KK];  // 1920
    int b = blockIdx.x;
    int tid = threadIdx.x;
    for (int i = tid; i < Ee * KK; i += 256) sRel[i] = rel[(long long)b * Ee * KK + i];
    __syncthreads();

    int d = tid & 127;
    int g = tid >> 7;
    float acc[8];
    #pragma unroll
    for (int ii = 0; ii < 8; ii++) acc[ii] = 0.f;
    long long mb = (long long)b * Nn * KK * OBS;
    for (int j = 0; j < Nn; j++) {
        float mj[KK];
        #pragma unroll
        for (int k = 0; k < KK; k++) mj[k] = msgs[mb + (j * KK + k) * OBS + d];
        #pragma unroll
        for (int ii = 0; ii < 8; ii++) {
            int i = g * 8 + ii;
            if (i == j) continue;
            int jj = (j < i) ? j : j - 1;
            const float* r = &sRel[(i * 15 + jj) * KK];
            float a = acc[ii];
            #pragma unroll
            for (int k = 0; k < KK; k++) a += r[k] * mj[k];
            acc[ii] = a;
        }
    }
    long long ab = (long long)b * Nn * 2 * OBS;
    #pragma unroll
    for (int ii = 0; ii < 8; ii++) {
        int i = g * 8 + ii;
        ai[ab + i * 2 * OBS + OBS + d] = acc[ii];
    }
    for (int idx = tid; idx < Nn * OBS; idx += 256) {
        int i = idx >> 7, dd = idx & 127;
        ai[ab + i * 2 * OBS + dd] = obs[(long long)b * Nn * OBS + idx];
    }
}

// ---------------- critic layer 2 (N=1): one warp per (b,n) dot ----------------
__global__ void critic2_k(const float* __restrict__ h1, const float* __restrict__ w2,
                          const float* __restrict__ b2v, float* __restrict__ out)
{
    int w = (blockIdx.x * blockDim.x + threadIdx.x) >> 5;
    int lane = threadIdx.x & 31;
    if (w >= BN_) return;
    int n = w & 15;
    float s = 0.f;
    #pragma unroll
    for (int q = 0; q < 8; q++) {
        int c = lane + 32 * q;
        s += h1[(long long)w * 512 + 256 + c] * w2[n * 256 + c];
    }
    #pragma unroll
    for (int off = 16; off; off >>= 1) s += __shfl_xor_sync(0xffffffffu, s, off);
    if (lane == 0) out[w] = s + b2v[n];
}

// ---------------- launch ----------------
extern "C" void kernel_launch(void* const* d_in, const int* in_sizes, int n_in,
                              void* d_out, int out_size)
{
    const float* obs    = (const float*)d_in[0];
    const float* rew    = (const float*)d_in[1];
    const float* h0     = (const float*)d_in[2];
    const float* w_ih   = (const float*)d_in[3];
    const float* w_hh   = (const float*)d_in[4];
    const float* b_ih   = (const float*)d_in[5];
    const float* b_hh   = (const float*)d_in[6];
    const float* enc_w1 = (const float*)d_in[7];
    const float* enc_b1 = (const float*)d_in[8];
    const float* enc_w2 = (const float*)d_in[9];
    const float* enc_b2 = (const float*)d_in[10];
    const float* dec_w1 = (const float*)d_in[11];
    const float* dec_b1 = (const float*)d_in[12];
    const float* dec_w2 = (const float*)d_in[13];
    const float* dec_b2 = (const float*)d_in[14];
    const float* msg_w  = (const float*)d_in[15];
    const float* msg_b  = (const float*)d_in[16];
    const float* aw1    = (const float*)d_in[17];
    const float* ab1    = (const float*)d_in[18];
    const float* aw2    = (const float*)d_in[19];
    const float* ab2    = (const float*)d_in[20];
    const float* cw1    = (const float*)d_in[21];
    const float* cb1    = (const float*)d_in[22];
    const float* cw2    = (const float*)d_in[23];
    const float* cb2    = (const float*)d_in[24];
    float* out = (float*)d_out;

    float *pgx, *pgh, *pnode, *pS, *pmsgs, *pai, *ph1, *pw, *pb, *pw2, *pb2, *pwih, *pwihc;
    cudaGetSymbolAddress((void**)&pgx,   g_gx);
    cudaGetSymbolAddress((void**)&pgh,   g_gh);
    cudaGetSymbolAddress((void**)&pnode, g_node);
    cudaGetSymbolAddress((void**)&pS,    g_S);
    cudaGetSymbolAddress((void**)&pmsgs, g_msgs);
    cudaGetSymbolAddress((void**)&pai,   g_ai);
    cudaGetSymbolAddress((void**)&ph1,   g_h1);
    cudaGetSymbolAddress((void**)&pw,    g_pw);
    cudaGetSymbolAddress((void**)&pb,    g_pb);
    cudaGetSymbolAddress((void**)&pw2,   g_pw2);
    cudaGetSymbolAddress((void**)&pb2,   g_pb2);
    cudaGetSymbolAddress((void**)&pwih,  g_wih);
    cudaGetSymbolAddress((void**)&pwihc, g_wihc);

    float* actor  = out;                 // [B,N,32]    524288
    float* critic = out + 524288;        // [B,N,1]     16384
    float* scm    = out + 540672;        // [B,N,129]   2113536
    float* rel    = out + 2654208;       // [B,E,8]     1966080
    float* hid    = out + 4620288;       // [1,B*N,256] 4194304

    const float* NUL = (const float*)0;

    // weight packing (small)
    pack_wih_k<<<(768 * 128 + 255) / 256, 256>>>(w_ih, pwih, pwihc);
    pack_node_k<<<1024, 256>>>(enc_w1, enc_b1, dec_w1, dec_b1, pw, pb);
    pack_head_k<<<(16 * 512 * 256 + 255) / 256, 256>>>(aw1, ab1, cw1, cb1, pw2, pb2);

    // GRU: gx = obs @ Wih[:, :128]^T + rew*Wih[:,128] + b_ih ; gh = h0 @ Whh^T + b_hh
    gemm_tc<128,128,64,32><<<dim3(6, 128, 1), 256>>>(
        obs, 128, 0, pwih, 128, 0, b_ih, 0, 1.f, rew, pwihc, 1,
        pgx, 768, 0, BN_, 768, 128, 1.f, 0);
    gemm_tc<128,128,64,32><<<dim3(6, 128, 1), 256>>>(
        h0, 256, 0, w_hh, 256, 0, b_hh, 0, 1.f, NUL, NUL, 0,
        pgh, 768, 0, BN_, 768, 256, 1.f, 0);
    gru_gate4_k<<<(BN_ * 64 + 255) / 256, 256>>>(pgx, pgh, h0, hid);

    // packed node projections: [16384,1024] = hid @ pw^T + pb
    gemm_tc<128,128,64,32><<<dim3(8, 128, 1), 256>>>(
        hid, 256, 0, pw, 256, 0, pb, 0, 1.f, NUL, NUL, 0,
        pnode, 1024, 0, BN_, 1024, 256, 1.f, 0);

    edge_k<<<Bz, 256>>>(pnode, enc_w2, enc_b2, rel, pS);

    // scm_pred = (S @ dec_w2^T + 15*b2) / 15.000001
    gemm_tc<128,128,64,32><<<dim3(2, 128, 1), 256>>>(
        pS, 256, 0, dec_w2, 256, 0, dec_b2, 0, 15.0f, NUL, NUL, 0,
        scm, 129, 0, BN_, 129, 256, 1.f / 15.000001f, 0);

    // msgs: [16384,1024] = obs @ msg_w^T + msg_b
    gemm_tc<128,128,64,32><<<dim3(8, 128, 1), 256>>>(
        obs, 128, 0, msg_w, 128, 0, msg_b, 0, 1.f, NUL, NUL, 0,
        pmsgs, 1024, 0, BN_, 1024, 128, 1.f, 0);

    message_k<<<Bz, 256>>>(rel, pmsgs, obs, pai);

    // fused actor+critic layer 1, batched over agent: [1024,512] per agent
    gemm_tc<128,128,64,32><<<dim3(4, 8, 16), 256>>>(
        pai, 4096, 256, pw2, 256, 512 * 256, pb2, 512, 1.f, NUL, NUL, 0,
        ph1, 8192, 512, Bz, 512, 256, 1.f, 1);

    // actor layer 2 (N=32), batched over agent
    gemm_tc<128,32,64,16><<<dim3(1, 8, 16), 128>>>(
        ph1, 8192, 512, aw2, 256, 32 * 256, ab2, 32, 1.f, NUL, NUL, 0,
        actor, 512, 32, Bz, 32, 256, 1.f, 0);

    critic2_k<<<BN_ / 8, 256>>>(ph1, cw2, cb2, critic);
}

// round 7
// speedup vs baseline: 2.9454x; 1.2895x over previous
#include <cuda_runtime.h>
#include <cuda_fp16.h>
#include <math.h>
#include <string.h>

#define Bz   1024
#define Nn   16
#define OBS  128
#define ACTD 32
#define RH   256
#define SH   256
#define KK   8
#define Ee   240
#define BN_  (Bz*Nn)   // 16384

// ---------------- scratch (__device__ globals; no allocation) ----------------
__device__ float g_gx  [BN_*768];
__device__ float g_gh  [BN_*768];
__device__ float g_node[BN_*1024];
__device__ float g_S   [BN_*SH];
__device__ float g_msgs[BN_*KK*OBS];
__device__ float g_ai  [BN_*2*OBS];
__device__ float g_h1  [BN_*512];
__device__ float g_pw  [1024*256];
__device__ float g_pb  [1024];
__device__ float g_pw2 [16*512*256];
__device__ float g_pb2 [16*512];
__device__ float g_wih [768*128];
__device__ float g_wihc[768];

// ---------------- helpers ----------------
__device__ __forceinline__ unsigned smem_u32(const void* p) {
    unsigned a;
    asm("{ .reg .u64 t; cvta.to.shared.u64 t, %1; cvt.u32.u64 %0, t; }" : "=r"(a) : "l"(p));
    return a;
}

__device__ __forceinline__ unsigned h2u(__half2 h) {
    unsigned u;
    memcpy(&u, &h, 4);
    return u;
}

__device__ __forceinline__ void mma_fp16(float* c, const unsigned* a, const unsigned* b) {
    asm volatile(
        "mma.sync.aligned.m16n8k16.row.col.f32.f16.f16.f32 "
        "{%0,%1,%2,%3}, {%4,%5,%6,%7}, {%8,%9}, {%0,%1,%2,%3};"
        : "+f"(c[0]), "+f"(c[1]), "+f"(c[2]), "+f"(c[3])
        : "r"(a[0]), "r"(a[1]), "r"(a[2]), "r"(a[3]), "r"(b[0]), "r"(b[1]));
}

__device__ __forceinline__ void ldsm4(unsigned* r, unsigned addr) {
    asm volatile("ldmatrix.sync.aligned.m8n8.x4.shared.b16 {%0,%1,%2,%3}, [%4];"
                 : "=r"(r[0]), "=r"(r[1]), "=r"(r[2]), "=r"(r[3]) : "r"(addr));
}

// ---------------- fp16 tensor-core GEMM (ldmatrix + double buffer)
// C = (A@B^T + bias*biasMul + rowv*colv)*scale [,relu]
// A:[M,K] lda row-major; B:[N,K] ldb row-major; z-batched via strides.
// Block 128x128, BK=32. Requires M%128==0, K%32==0, lda/ldb%4==0.
#define SROW 40                      // fp16 row stride (80 bytes) -> LDSM conflict-free
#define ATB  (128 * SROW * 2)        // 10240 bytes per operand tile

__global__ void __launch_bounds__(256, 2) gemm_h(
    const float* __restrict__ A, int lda, long long sA,
    const float* __restrict__ B, int ldb, long long sB,
    const float* __restrict__ bias, long long sBias, float biasMul,
    const float* __restrict__ rowv, const float* __restrict__ colv, int cvs,
    float* __restrict__ C, int ldc, long long sC,
    int M, int N, int K, float scale, int relu)
{
    __shared__ __align__(16) char sm[2][2 * ATB];   // [buf][A|B]

    int t = threadIdx.x;
    int wid = t >> 5, lane = t & 31;
    int bz = blockIdx.z;
    A += (long long)bz * sA;
    B += (long long)bz * sB;
    C += (long long)bz * sC;
    const float* bp = bias ? bias + (long long)bz * sBias : (const float*)0;
    int row0 = blockIdx.y * 128;
    int col0 = blockIdx.x * 128;

    int wm0 = (wid & 1) * 64;        // 2 warps in M
    int wn0 = (wid >> 1) * 32;       // 4 warps in N
    int mrow = lane >> 2, kr = lane & 3;

    float acc[16][4];
    #pragma unroll
    for (int i = 0; i < 16; i++)
        #pragma unroll
        for (int j = 0; j < 4; j++) acc[i][j] = 0.f;

    // staging slice: idx = q*256 + t; row = idx>>2 (0..127), g = idx&3 (k-octet)
    int srow = t >> 2, sg = t & 3;           // q=0 slice
    int srow1 = srow + 64, sg1 = sg;         // q=1 slice

    unsigned pa[2][4], pbv[2][4];

    // ---- prologue: load + convert chunk 0 ----
    {
        #pragma unroll
        for (int q = 0; q < 2; q++) {
            int r = (q ? srow1 : srow), g = (q ? sg1 : sg);
            const float* ap = A + (long long)(row0 + r) * lda + g * 8;
            float4 v0 = *(const float4*)ap;
            float4 v1 = *(const float4*)(ap + 4);
            pa[q][0] = h2u(__floats2half2_rn(v0.x, v0.y));
            pa[q][1] = h2u(__floats2half2_rn(v0.z, v0.w));
            pa[q][2] = h2u(__floats2half2_rn(v1.x, v1.y));
            pa[q][3] = h2u(__floats2half2_rn(v1.z, v1.w));
            int gc = col0 + r;
            float4 w0 = make_float4(0.f, 0.f, 0.f, 0.f), w1 = w0;
            if (gc < N) {
                const float* bpn = B + (long long)gc * ldb + g * 8;
                w0 = *(const float4*)bpn;
                w1 = *(const float4*)(bpn + 4);
            }
            pbv[q][0] = h2u(__floats2half2_rn(w0.x, w0.y));
            pbv[q][1] = h2u(__floats2half2_rn(w0.z, w0.w));
            pbv[q][2] = h2u(__floats2half2_rn(w1.x, w1.y));
            pbv[q][3] = h2u(__floats2half2_rn(w1.z, w1.w));
        }
        #pragma unroll
        for (int q = 0; q < 2; q++) {
            int r = (q ? srow1 : srow), g = (q ? sg1 : sg);
            *(uint4*)(sm[0] + r * 80 + g * 16)       = make_uint4(pa[q][0], pa[q][1], pa[q][2], pa[q][3]);
            *(uint4*)(sm[0] + ATB + r * 80 + g * 16) = make_uint4(pbv[q][0], pbv[q][1], pbv[q][2], pbv[q][3]);
        }
    }
    __syncthreads();

    unsigned sbaseA = smem_u32(sm);
    int buf = 0;
    for (int k0 = 0; k0 < K; k0 += 32) {
        bool next = (k0 + 32) < K;
        if (next) {
            int kn = k0 + 32;
            #pragma unroll
            for (int q = 0; q < 2; q++) {
                int r = (q ? srow1 : srow), g = (q ? sg1 : sg);
                const float* ap = A + (long long)(row0 + r) * lda + kn + g * 8;
                float4 v0 = *(const float4*)ap;
                float4 v1 = *(const float4*)(ap + 4);
                pa[q][0] = h2u(__floats2half2_rn(v0.x, v0.y));
                pa[q][1] = h2u(__floats2half2_rn(v0.z, v0.w));
                pa[q][2] = h2u(__floats2half2_rn(v1.x, v1.y));
                pa[q][3] = h2u(__floats2half2_rn(v1.z, v1.w));
                int gc = col0 + r;
                float4 w0 = make_float4(0.f, 0.f, 0.f, 0.f), w1 = w0;
                if (gc < N) {
                    const float* bpn = B + (long long)gc * ldb + kn + g * 8;
                    w0 = *(const float4*)bpn;
                    w1 = *(const float4*)(bpn + 4);
                }
                pbv[q][0] = h2u(__floats2half2_rn(w0.x, w0.y));
                pbv[q][1] = h2u(__floats2half2_rn(w0.z, w0.w));
                pbv[q][2] = h2u(__floats2half2_rn(w1.x, w1.y));
                pbv[q][3] = h2u(__floats2half2_rn(w1.z, w1.w));
            }
        }

        // compute current buffer: 2 k16-steps
        unsigned abase = sbaseA + buf * (2 * ATB);
        unsigned bbase = abase + ATB;
        int tl = lane >> 3, rl = lane & 7;   // ldsm tile index, row-in-tile
        #pragma unroll
        for (int s = 0; s < 2; s++) {
            int ks = s * 16;
            unsigned afr[4][4], bfr[4][2];
            #pragma unroll
            for (int mt = 0; mt < 4; mt++) {
                int m0 = wm0 + mt * 16;
                int row = m0 + rl + ((tl & 1) << 3);
                int col = ks + ((tl >> 1) << 3);
                ldsm4(afr[mt], abase + row * 80 + col * 2);
            }
            #pragma unroll
            for (int nb = 0; nb < 2; nb++) {
                int n0 = wn0 + nb * 16;
                int row = n0 + rl + ((tl >> 1) << 3);
                int col = ks + ((tl & 1) << 3);
                unsigned r4[4];
                ldsm4(r4, bbase + row * 80 + col * 2);
                bfr[nb * 2 + 0][0] = r4[0]; bfr[nb * 2 + 0][1] = r4[1];
                bfr[nb * 2 + 1][0] = r4[2]; bfr[nb * 2 + 1][1] = r4[3];
            }
            #pragma unroll
            for (int mt = 0; mt < 4; mt++)
                #pragma unroll
                for (int nt = 0; nt < 4; nt++)
                    mma_fp16(acc[mt * 4 + nt], afr[mt], bfr[nt]);
        }

        if (next) {
            char* nb_ = sm[buf ^ 1];
            #pragma unroll
            for (int q = 0; q < 2; q++) {
                int r = (q ? srow1 : srow), g = (q ? sg1 : sg);
                *(uint4*)(nb_ + r * 80 + g * 16)       = make_uint4(pa[q][0], pa[q][1], pa[q][2], pa[q][3]);
                *(uint4*)(nb_ + ATB + r * 80 + g * 16) = make_uint4(pbv[q][0], pbv[q][1], pbv[q][2], pbv[q][3]);
            }
        }
        __syncthreads();
        buf ^= 1;
    }

    // ---- epilogue ----
    #pragma unroll
    for (int mt = 0; mt < 4; mt++) {
        int r0 = row0 + wm0 + mt * 16 + mrow;
        #pragma unroll
        for (int nt = 0; nt < 4; nt++) {
            int cbase = col0 + wn0 + nt * 8 + 2 * kr;
            const float* cc = acc[mt * 4 + nt];
            #pragma unroll
            for (int h = 0; h < 2; h++) {
                int gr = r0 + h * 8;
                #pragma unroll
                for (int w2 = 0; w2 < 2; w2++) {
                    int gc = cbase + w2;
                    if (gc < N) {
                        float v = cc[h * 2 + w2];
                        if (bp) v += bp[gc] * biasMul;
                        if (rowv) v += rowv[gr] * colv[(long long)gc * cvs];
                        v *= scale;
                        if (relu) v = fmaxf(v, 0.f);
                        C[(long long)gr * ldc + gc] = v;
                    }
                }
            }
        }
    }
}

// ---------------- pack w_ih [768,129] -> aligned [768,128] + column 128 ----------------
__global__ void pack_wih_k(const float* __restrict__ w_ih,
                           float* __restrict__ wp, float* __restrict__ wc)
{
    int idx = blockIdx.x * 256 + threadIdx.x;
    if (idx < 768 * 128) {
        int r = idx >> 7, c = idx & 127;
        wp[idx] = w_ih[r * 129 + c];
    }
    if (idx < 768) wc[idx] = w_ih[idx * 129 + 128];
}

// ---------------- pack node-projection weights: pw [1024,256], pb[1024] ----------------
__global__ void pack_node_k(const float* __restrict__ ew1, const float* __restrict__ eb1,
                            const float* __restrict__ dw1, const float* __restrict__ db1,
                            float* __restrict__ pw, float* __restrict__ pb)
{
    int idx = blockIdx.x * 256 + threadIdx.x;
    if (idx < 1024 * 256) {
        int r = idx >> 8, c = idx & 255;
        float v;
        if (r < 256)      v = ew1[r * 512 + c];
        else if (r < 512) v = ew1[(r - 256) * 512 + 256 + c];
        else if (r < 768) v = dw1[(r - 512) * 512 + c];
        else              v = dw1[(r - 768) * 512 + 256 + c];
        pw[idx] = v;
    }
    if (idx < 1024) {
        int r = idx;
        float v = 0.f;
        if (r >= 256 && r < 512) v = eb1[r - 256];
        else if (r >= 768)       v = db1[r - 768];
        pb[r] = v;
    }
}

// ---------------- pack head layer-1 weights: pw2 [16,512,256], pb2[16,512] ----------------
__global__ void pack_head_k(const float* __restrict__ aw1, const float* __restrict__ ab1,
                            const float* __restrict__ cw1, const float* __restrict__ cb1,
                            float* __restrict__ pw2, float* __restrict__ pb2)
{
    int idx = blockIdx.x * 256 + threadIdx.x;
    if (idx < 16 * 512 * 256) {
        int n = idx >> 17;
        int r = (idx >> 8) & 511;
        int c = idx & 255;
        float v = (r < 256) ? aw1[n * 65536 + r * 256 + c]
                            : cw1[n * 65536 + (r - 256) * 256 + c];
        pw2[idx] = v;
    }
    if (idx < 16 * 512) {
        int n = idx >> 9, r = idx & 511;
        pb2[idx] = (r < 256) ? ab1[n * 256 + r] : cb1[n * 256 + r - 256];
    }
}

// ---------------- GRU gates (float4) ----------------
__global__ void gru_gate4_k(const float* __restrict__ gx, const float* __restrict__ gh,
                            const float* __restrict__ h0, float* __restrict__ h)
{
    int idx = blockIdx.x * blockDim.x + threadIdx.x;  // over BN_*64
    if (idx >= BN_ * 64) return;
    int m = idx >> 6;
    int c4 = (idx & 63) * 4;
    long long bx = (long long)m * 768 + c4;
    float4 xr = *(const float4*)(gx + bx);
    float4 xz = *(const float4*)(gx + bx + 256);
    float4 xn = *(const float4*)(gx + bx + 512);
    float4 hr = *(const float4*)(gh + bx);
    float4 hz = *(const float4*)(gh + bx + 256);
    float4 hn = *(const float4*)(gh + bx + 512);
    float4 h0v = *(const float4*)(h0 + (long long)m * 256 + c4);
    float4 o;
    {
        float r = 1.f / (1.f + expf(-(xr.x + hr.x)));
        float z = 1.f / (1.f + expf(-(xz.x + hz.x)));
        float nc = tanhf(xn.x + r * hn.x);
        o.x = (1.f - z) * nc + z * h0v.x;
    }
    {
        float r = 1.f / (1.f + expf(-(xr.y + hr.y)));
        float z = 1.f / (1.f + expf(-(xz.y + hz.y)));
        float nc = tanhf(xn.y + r * hn.y);
        o.y = (1.f - z) * nc + z * h0v.y;
    }
    {
        float r = 1.f / (1.f + expf(-(xr.z + hr.z)));
        float z = 1.f / (1.f + expf(-(xz.z + hz.z)));
        float nc = tanhf(xn.z + r * hn.z);
        o.z = (1.f - z) * nc + z * h0v.z;
    }
    {
        float r = 1.f / (1.f + expf(-(xr.w + hr.w)));
        float z = 1.f / (1.f + expf(-(xz.w + hz.w)));
        float nc = tanhf(xn.w + r * hn.w);
        o.w = (1.f - z) * nc + z * h0v.w;
    }
    *(float4*)(h + (long long)m * 256 + c4) = o;
}

// ---------------- fused per-batch edge kernel (reads packed node projections) ----------------
__global__ __launch_bounds__(256) void edge_k(
    const float* __restrict__ node,          // [B*N, 1024]: eHs|eHr|dHs|dHr
    const float* __restrict__ w2, const float* __restrict__ b2,
    float* __restrict__ rel, float* __restrict__ Sout)
{
    __shared__ float sW2[KK * SH];
    __shared__ float sS[Nn][SH];
    int b = blockIdx.x;
    int tid = threadIdx.x;
    for (int i = tid; i < KK * SH; i += 256) sW2[i] = w2[i];
    for (int i = tid; i < Nn * SH; i += 256) (&sS[0][0])[i] = 0.f;
    __syncthreads();

    int w = tid >> 5, lane = tid & 31;
    long long base = (long long)b * Nn * 1024;
    for (int ii = 0; ii < 2; ii++) {
        int i = w * 2 + ii;
        float eR[8], dR[8];
        #pragma unroll
        for (int q = 0; q < 8; q++) {
            int c = lane + 32 * q;
            eR[q] = node[base + i * 1024 + 256 + c];
            dR[q] = node[base + i * 1024 + 768 + c];
        }
        for (int j = 0; j < Nn; j++) {
            if (j == i) continue;
            float part[KK];
            #pragma unroll
            for (int k = 0; k < KK; k++) part[k] = 0.f;
            #pragma unroll
            for (int q = 0; q < 8; q++) {
                int c = lane + 32 * q;
                float pe = node[base + j * 1024 + c] + eR[q];
                pe = fmaxf(pe, 0.f);
                #pragma unroll
                for (int k = 0; k < KK; k++) part[k] += pe * sW2[k * SH + c];
                float pd = node[base + j * 1024 + 512 + c] + dR[q];
                pd = fmaxf(pd, 0.f);
                sS[i][c] += pd;
            }
            #pragma unroll
            for (int k = 0; k < KK; k++) {
                #pragma unroll
                for (int off = 16; off; off >>= 1)
                    part[k] += __shfl_xor_sync(0xffffffffu, part[k], off);
                part[k] += b2[k];
            }
            if (lane == 0) {
                float mx = part[0];
                #pragma unroll
                for (int k = 1; k < KK; k++) mx = fmaxf(mx, part[k]);
                float e_[KK], s = 0.f;
                #pragma unroll
                for (int k = 0; k < KK; k++) { e_[k] = expf(part[k] - mx); s += e_[k]; }
                float inv = 1.f / s;
                int jj = (j < i) ? j : j - 1;
                long long eo = ((long long)b * Ee + i * 15 + jj) * KK;
                #pragma unroll
                for (int k = 0; k < KK; k++) rel[eo + k] = e_[k] * inv;
            }
        }
    }
    __syncthreads();
    long long sb = (long long)b * Nn * SH;
    for (int i = tid; i < Nn * SH; i += 256)
        Sout[sb + i] = (&sS[0][0])[i];
}

// ---------------- message aggregation + build ai = [obs, message] ----------------
__global__ __launch_bounds__(256) void message_k(
    const float* __restrict__ rel, const float* __restrict__ msgs,
    const float* __restrict__ obs, float* __restrict__ ai)
{
    __shared__ float sRel[Ee * KK];  // 1920
    int b = blockIdx.x;
    int tid = threadIdx.x;
    for (int i = tid; i < Ee * KK; i += 256) sRel[i] = rel[(long long)b * Ee * KK + i];
    __syncthreads();

    int d = tid & 127;
    int g = tid >> 7;
    float acc[8];
    #pragma unroll
    for (int ii = 0; ii < 8; ii++) acc[ii] = 0.f;
    long long mb = (long long)b * Nn * KK * OBS;
    for (int j = 0; j < Nn; j++) {
        float mj[KK];
        #pragma unroll
        for (int k = 0; k < KK; k++) mj[k] = msgs[mb + (j * KK + k) * OBS + d];
        #pragma unroll
        for (int ii = 0; ii < 8; ii++) {
            int i = g * 8 + ii;
            if (i == j) continue;
            int jj = (j < i) ? j : j - 1;
            const float* r = &sRel[(i * 15 + jj) * KK];
            float a = acc[ii];
            #pragma unroll
            for (int k = 0; k < KK; k++) a += r[k] * mj[k];
            acc[ii] = a;
        }
    }
    long long ab = (long long)b * Nn * 2 * OBS;
    #pragma unroll
    for (int ii = 0; ii < 8; ii++) {
        int i = g * 8 + ii;
        ai[ab + i * 2 * OBS + OBS + d] = acc[ii];
    }
    for (int idx = tid; idx < Nn * OBS; idx += 256) {
        int i = idx >> 7, dd = idx & 127;
        ai[ab + i * 2 * OBS + dd] = obs[(long long)b * Nn * OBS + idx];
    }
}

// ---------------- critic layer 2 (N=1): one warp per (b,n) dot ----------------
__global__ void critic2_k(const float* __restrict__ h1, const float* __restrict__ w2,
                          const float* __restrict__ b2v, float* __restrict__ out)
{
    int w = (blockIdx.x * blockDim.x + threadIdx.x) >> 5;
    int lane = threadIdx.x & 31;
    if (w >= BN_) return;
    int n = w & 15;
    float s = 0.f;
    #pragma unroll
    for (int q = 0; q < 8; q++) {
        int c = lane + 32 * q;
        s += h1[(long long)w * 512 + 256 + c] * w2[n * 256 + c];
    }
    #pragma unroll
    for (int off = 16; off; off >>= 1) s += __shfl_xor_sync(0xffffffffu, s, off);
    if (lane == 0) out[w] = s + b2v[n];
}

// ---------------- launch ----------------
extern "C" void kernel_launch(void* const* d_in, const int* in_sizes, int n_in,
                              void* d_out, int out_size)
{
    const float* obs    = (const float*)d_in[0];
    const float* rew    = (const float*)d_in[1];
    const float* h0     = (const float*)d_in[2];
    const float* w_ih   = (const float*)d_in[3];
    const float* w_hh   = (const float*)d_in[4];
    const float* b_ih   = (const float*)d_in[5];
    const float* b_hh   = (const float*)d_in[6];
    const float* enc_w1 = (const float*)d_in[7];
    const float* enc_b1 = (const float*)d_in[8];
    const float* enc_w2 = (const float*)d_in[9];
    const float* enc_b2 = (const float*)d_in[10];
    const float* dec_w1 = (const float*)d_in[11];
    const float* dec_b1 = (const float*)d_in[12];
    const float* dec_w2 = (const float*)d_in[13];
    const float* dec_b2 = (const float*)d_in[14];
    const float* msg_w  = (const float*)d_in[15];
    const float* msg_b  = (const float*)d_in[16];
    const float* aw1    = (const float*)d_in[17];
    const float* ab1    = (const float*)d_in[18];
    const float* aw2    = (const float*)d_in[19];
    const float* ab2    = (const float*)d_in[20];
    const float* cw1    = (const float*)d_in[21];
    const float* cb1    = (const float*)d_in[22];
    const float* cw2    = (const float*)d_in[23];
    const float* cb2    = (const float*)d_in[24];
    float* out = (float*)d_out;

    float *pgx, *pgh, *pnode, *pS, *pmsgs, *pai, *ph1, *pw, *pb, *pw2, *pb2, *pwih, *pwihc;
    cudaGetSymbolAddress((void**)&pgx,   g_gx);
    cudaGetSymbolAddress((void**)&pgh,   g_gh);
    cudaGetSymbolAddress((void**)&pnode, g_node);
    cudaGetSymbolAddress((void**)&pS,    g_S);
    cudaGetSymbolAddress((void**)&pmsgs, g_msgs);
    cudaGetSymbolAddress((void**)&pai,   g_ai);
    cudaGetSymbolAddress((void**)&ph1,   g_h1);
    cudaGetSymbolAddress((void**)&pw,    g_pw);
    cudaGetSymbolAddress((void**)&pb,    g_pb);
    cudaGetSymbolAddress((void**)&pw2,   g_pw2);
    cudaGetSymbolAddress((void**)&pb2,   g_pb2);
    cudaGetSymbolAddress((void**)&pwih,  g_wih);
    cudaGetSymbolAddress((void**)&pwihc, g_wihc);

    float* actor  = out;                 // [B,N,32]    524288
    float* critic = out + 524288;        // [B,N,1]     16384
    float* scm    = out + 540672;        // [B,N,129]   2113536
    float* rel    = out + 2654208;       // [B,E,8]     1966080
    float* hid    = out + 4620288;       // [1,B*N,256] 4194304

    const float* NUL = (const float*)0;

    // weight packing (small)
    pack_wih_k<<<(768 * 128 + 255) / 256, 256>>>(w_ih, pwih, pwihc);
    pack_node_k<<<1024, 256>>>(enc_w1, enc_b1, dec_w1, dec_b1, pw, pb);
    pack_head_k<<<(16 * 512 * 256 + 255) / 256, 256>>>(aw1, ab1, cw1, cb1, pw2, pb2);

    // GRU: gx = obs @ Wih[:, :128]^T + rew*Wih[:,128] + b_ih ; gh = h0 @ Whh^T + b_hh
    gemm_h<<<dim3(6, 128, 1), 256>>>(
        obs, 128, 0, pwih, 128, 0, b_ih, 0, 1.f, rew, pwihc, 1,
        pgx, 768, 0, BN_, 768, 128, 1.f, 0);
    gemm_h<<<dim3(6, 128, 1), 256>>>(
        h0, 256, 0, w_hh, 256, 0, b_hh, 0, 1.f, NUL, NUL, 0,
        pgh, 768, 0, BN_, 768, 256, 1.f, 0);
    gru_gate4_k<<<(BN_ * 64 + 255) / 256, 256>>>(pgx, pgh, h0, hid);

    // packed node projections: [16384,1024] = hid @ pw^T + pb
    gemm_h<<<dim3(8, 128, 1), 256>>>(
        hid, 256, 0, pw, 256, 0, pb, 0, 1.f, NUL, NUL, 0,
        pnode, 1024, 0, BN_, 1024, 256, 1.f, 0);

    edge_k<<<Bz, 256>>>(pnode, enc_w2, enc_b2, rel, pS);

    // scm_pred = (S @ dec_w2^T + 15*b2) / 15.000001
    gemm_h<<<dim3(2, 128, 1), 256>>>(
        pS, 256, 0, dec_w2, 256, 0, dec_b2, 0, 15.0f, NUL, NUL, 0,
        scm, 129, 0, BN_, 129, 256, 1.f / 15.000001f, 0);

    // msgs: [16384,1024] = obs @ msg_w^T + msg_b
    gemm_h<<<dim3(8, 128, 1), 256>>>(
        obs, 128, 0, msg_w, 128, 0, msg_b, 0, 1.f, NUL, NUL, 0,
        pmsgs, 1024, 0, BN_, 1024, 128, 1.f, 0);

    message_k<<<Bz, 256>>>(rel, pmsgs, obs, pai);

    // fused actor+critic layer 1, batched over agent: [1024,512] per agent
    gemm_h<<<dim3(4, 8, 16), 256>>>(
        pai, 4096, 256, pw2, 256, 512 * 256, pb2, 512, 1.f, NUL, NUL, 0,
        ph1, 8192, 512, Bz, 512, 256, 1.f, 1);

    // actor layer 2 (N=32), batched over agent
    gemm_h<<<dim3(1, 8, 16), 256>>>(
        ph1, 8192, 512, aw2, 256, 32 * 256, ab2, 32, 1.f, NUL, NUL, 0,
        actor, 512, 32, Bz, 32, 256, 1.f, 0);

    critic2_k<<<BN_ / 8, 256>>>(ph1, cw2, cb2, critic);
}